// round 7
// baseline (speedup 1.0000x reference)
#include <cuda_runtime.h>

// Fully fused 4x upsampler, two halfband-polyphase 2x stages, no mid tensor.
// P2 is packed over ROW PAIRS (i, i+24) in f32x2; P3 is packed over the
// (copy-col, interp-col) output pair. All 12-tap chains split 6+6 for latency.

typedef unsigned long long ull;

#define FMA2(d, a, b, c) \
    asm("fma.rn.f32x2 %0, %1, %2, %3;" : "=l"(d) : "l"(a), "l"(b), "l"(c))
#define ADD2(d, a, b) \
    asm("add.rn.f32x2 %0, %1, %2;" : "=l"(d) : "l"(a), "l"(b))
#define PK2(d, lo, hi) \
    asm("mov.b64 %0, {%1, %2};" : "=l"(d) : "f"(lo), "f"(hi))
#define UPK2(lo, hi, s) \
    asm("mov.b64 {%0, %1}, %2;" : "=f"(lo), "=f"(hi) : "l"(s))

#define XS 52   // x row stride (floats)
#define CS 65   // s_c row stride (8-byte elems, odd -> conflict-free)
#define W2(u) w2[(u) < 6 ? (u) : 11 - (u)]   // halfband taps are symmetric

__global__ __launch_bounds__(256) void fused_up4x(
    const float* __restrict__ in, const float* __restrict__ kern,
    float* __restrict__ out)
{
    __shared__ __align__(16) float s_x[48 * XS]; // x rows: local i <-> 32*by-8+i
    __shared__ ull  s_c[48 * CS];                // packed (copy-col, q) per col-pair
    __shared__ float s_w[12];

    const int ch = blockIdx.z, by = blockIdx.y, bx = blockIdx.x;
    const float* inc  = in  + ch * 65536;
    float*       outc = out + ch * 1048576;
    const int tid = threadIdx.x;
    if (tid < 12) s_w[tid] = kern[2 * tid];

    // ---- P1: load 48x48 x tile (base -8, circular wrap mod 256) ----
#pragma unroll
    for (int t = 0; t < 9; t++) {
        int idx = tid + 256 * t;
        if (idx < 2304) {
            int i = idx / 48, j = idx - i * 48;
            int gr = (32 * by - 8 + i) & 255;
            int gc = (32 * bx - 8 + j) & 255;
            s_x[i * XS + j] = inc[gr * 256 + gc];
        }
    }
    __syncthreads();

    float w[12];
#pragma unroll
    for (int u = 0; u < 12; u++) w[u] = s_w[u];
    ull w2[6];
#pragma unroll
    for (int u = 0; u < 6; u++) PK2(w2[u], w[u], w[u]);

    // ---- P2: row-pair packed. unit=(row pair i/i+24, chunk g). 96 units. ----
    if (tid < 96) {
        const int i = tid % 24, g = tid / 24;
        const float4* pa = reinterpret_cast<const float4*>(&s_x[i * XS + 8 * g]);
        const float4* pb = reinterpret_cast<const float4*>(&s_x[(i + 24) * XS + 8 * g]);
        ull X2[24];
#pragma unroll
        for (int q = 0; q < 6; q++) {
            float4 a = pa[q], b = pb[q];
            PK2(X2[4*q + 0], a.x, b.x); PK2(X2[4*q + 1], a.y, b.y);
            PK2(X2[4*q + 2], a.z, b.z); PK2(X2[4*q + 3], a.w, b.w);
        }
        ull H2[13];
#pragma unroll
        for (int d = 0; d < 13; d++) {
            ull a = 0ull, b = 0ull;
#pragma unroll
            for (int u = 0; u < 6; u++)  FMA2(a, w2[u],      X2[d + u], a);
#pragma unroll
            for (int u = 6; u < 12; u++) FMA2(b, w2[11 - u], X2[d + u], b);
            ADD2(H2[d], a, b);
        }
#pragma unroll
        for (int m = 0; m < 16; m++) {
            ull xa = 0ull, ha = 0ull;
            if (m & 1) {
#pragma unroll
                for (int e = 0; e < 6; e++) {
                    FMA2(xa, W2(2*e + 1), X2[(m + 1)/2 + 5 + e], xa);
                    FMA2(ha, W2(2*e),     H2[(m - 1)/2 + e],     ha);
                }
            } else {
#pragma unroll
                for (int e = 0; e < 6; e++) {
                    FMA2(xa, W2(2*e),     X2[m/2 + 5 + e], xa);
                    FMA2(ha, W2(2*e + 1), H2[m/2 + e],     ha);
                }
            }
            ull qv2; ADD2(qv2, xa, ha);
            ull cv2 = (m & 1) ? X2[(m + 15) / 2] : H2[m / 2 + 2];
            float c0, c1, q0, q1;
            UPK2(c0, c1, cv2); UPK2(q0, q1, qv2);
            const int col = 16 * g + m;
            *reinterpret_cast<float2*>(&s_c[i * CS + col])        = make_float2(c0, q0);
            *reinterpret_cast<float2*>(&s_c[(i + 24) * CS + col]) = make_float2(c1, q1);
        }
    }
    __syncthreads();

    // ---- P3: emission, packed (copy,interp). thread=(col pair p, group g) ----
    {
        const int p = tid & 63, g = tid >> 6;
        const ull* pc = &s_c[(8 * g) * CS + p];
        float* ob = outc + (128 * by + 32 * g) * 1024 + 128 * bx + 2 * p;

        ull W[12];                           // rotating window, offset o -> [o%12]
#pragma unroll
        for (int o = 0; o < 12; o++) W[o] = pc[o * CS];

        ull acc[16];
#pragma unroll
        for (int k = 0; k < 16; k++) acc[k] = 0ull;

#pragma unroll
        for (int n = 0; n < 27; n++) {
            ull m2;
            if (n & 1) {
                if (n >= 3) {
                    const int onew = (n - 1) / 2 + 11;
                    W[onew % 12] = pc[onew * CS];
                }
                const int k0 = (n - 1) >> 1;
                ull a = 0ull, b = 0ull;
#pragma unroll
                for (int u = 0; u < 6; u++)  FMA2(a, w2[u],      W[(k0 + u) % 12], a);
#pragma unroll
                for (int u = 6; u < 12; u++) FMA2(b, w2[11 - u], W[(k0 + u) % 12], b);
                ADD2(m2, a, b);
            } else {
                m2 = W[(n / 2 + 5) % 12];
            }
#pragma unroll
            for (int k = 0; k < 16; k++) {
                const int u = n - k;
                if (u >= 0 && u < 12) FMA2(acc[k], W2(u), m2, acc[k]);
            }
            if (n >= 5 && n < 21)            // even output rows: direct copy
                *reinterpret_cast<ull*>(&ob[(2 * (n - 5)) * 1024]) = m2;
        }
#pragma unroll
        for (int k = 0; k < 16; k++)         // odd output rows: V-interp
            *reinterpret_cast<ull*>(&ob[(2 * k + 1) * 1024]) = acc[k];
    }
}

extern "C" void kernel_launch(void* const* d_in, const int* in_sizes, int n_in,
                              void* d_out, int out_size)
{
    const float* x    = (const float*)d_in[0];   // (4,8,256,256) fp32
    const float* kern = (const float*)d_in[1];   // 23 taps fp32
    float* out = (float*)d_out;                  // (4,8,1024,1024) fp32

    fused_up4x<<<dim3(8, 8, 32), 256>>>(x, kern, out);
}

// round 8
// speedup vs baseline: 1.2748x; 1.2748x over previous
#include <cuda_runtime.h>

// Fully fused 4x upsampler, two halfband-polyphase 2x stages, no mid tensor.
// Round-6 structure (scalar P2, packed-(copy,interp) P3) + 64-reg budget,
// in-loop accumulator retirement, and 6+6 split FMA chains.

typedef unsigned long long ull;

#define FMA2(d, a, b, c) \
    asm("fma.rn.f32x2 %0, %1, %2, %3;" : "=l"(d) : "l"(a), "l"(b), "l"(c))
#define ADD2(d, a, b) \
    asm("add.rn.f32x2 %0, %1, %2;" : "=l"(d) : "l"(a), "l"(b))
#define PK2(d, lo, hi) \
    asm("mov.b64 %0, {%1, %2};" : "=l"(d) : "f"(lo), "f"(hi))

#define XS 52   // x row stride (floats), conflict-free LDS.128
#define CS 65   // s_c row stride (8-byte elems, odd -> conflict-free LDS.64)
#define W2(u) w2[(u) < 6 ? (u) : 11 - (u)]   // halfband taps are symmetric

__global__ __launch_bounds__(256, 4) void fused_up4x(
    const float* __restrict__ in, const float* __restrict__ kern,
    float* __restrict__ out)
{
    __shared__ __align__(16) float s_x[48 * XS]; // x rows: local i <-> 32*by-8+i
    __shared__ ull  s_c[48 * CS];                // packed (copy-col, q) per col-pair
    __shared__ float s_w[12];

    const int ch = blockIdx.z, by = blockIdx.y, bx = blockIdx.x;
    const float* inc  = in  + ch * 65536;
    float*       outc = out + ch * 1048576;
    const int tid = threadIdx.x;
    if (tid < 12) s_w[tid] = kern[2 * tid];

    // ---- P1: load 48x48 x tile (base -8, circular wrap mod 256) ----
#pragma unroll
    for (int t = 0; t < 9; t++) {
        int idx = tid + 256 * t;
        if (idx < 2304) {
            int i = idx / 48, j = idx - i * 48;
            int gr = (32 * by - 8 + i) & 255;
            int gc = (32 * bx - 8 + j) & 255;
            s_x[i * XS + j] = inc[gr * 256 + gc];
        }
    }
    __syncthreads();

    float w[12];
#pragma unroll
    for (int u = 0; u < 12; u++) w[u] = s_w[u];
    ull w2[6];
#pragma unroll
    for (int u = 0; u < 6; u++) PK2(w2[u], w[u], w[u]);

    // ---- P2: per (row i, chunk g): H[13] + q[16] + copies -> packed s_c ----
    if (tid < 192) {
        const int i = tid % 48, g = tid / 48;
        float X[24];
        const float4* xp = reinterpret_cast<const float4*>(&s_x[i * XS + 8 * g]);
#pragma unroll
        for (int q = 0; q < 6; q++) {
            float4 t = xp[q];
            X[4*q] = t.x; X[4*q+1] = t.y; X[4*q+2] = t.z; X[4*q+3] = t.w;
        }
        float H[13];
#pragma unroll
        for (int d = 0; d < 13; d++) {
            float a = 0.f, b = 0.f;
#pragma unroll
            for (int u = 0; u < 6; u++)  a += w[u] * X[d + u];
#pragma unroll
            for (int u = 6; u < 12; u++) b += w[u] * X[d + u];
            H[d] = a + b;
        }
        // s_c[i][16g+m] = (copy value, q value) for output col-pair p=16g+m
#pragma unroll
        for (int m = 0; m < 16; m++) {
            float xa = 0.f, ha = 0.f;
            if (m & 1) {
#pragma unroll
                for (int e = 0; e < 6; e++) {
                    xa += w[2*e+1] * X[(m+1)/2 + 5 + e];
                    ha += w[2*e]   * H[(m-1)/2 + e];
                }
            } else {
#pragma unroll
                for (int e = 0; e < 6; e++) {
                    xa += w[2*e]   * X[m/2 + 5 + e];
                    ha += w[2*e+1] * H[m/2 + e];
                }
            }
            float qv = xa + ha;
            float cv = (m & 1) ? X[(m + 15) / 2] : H[m / 2 + 2];
            ull pv; PK2(pv, cv, qv);
            s_c[i * CS + 16 * g + m] = pv;
        }
    }
    __syncthreads();

    // ---- P3: emission, packed. thread = (col pair p in [0,64), group g) ----
    // Streams mid rows n=0..26; acc[k] retires (stored) at n == k+11.
    {
        const int p = tid & 63, g = tid >> 6;
        const ull* pc = &s_c[(8 * g) * CS + p];
        float* ob = outc + (128 * by + 32 * g) * 1024 + 128 * bx + 2 * p;

        ull W[12];                           // rotating window, offset o -> [o%12]
#pragma unroll
        for (int o = 0; o < 12; o++) W[o] = pc[o * CS];

        ull acc[16];
#pragma unroll
        for (int k = 0; k < 16; k++) acc[k] = 0ull;

#pragma unroll
        for (int n = 0; n < 27; n++) {
            ull m2;
            if (n & 1) {
                if (n >= 3) {
                    const int onew = (n - 1) / 2 + 11;
                    W[onew % 12] = pc[onew * CS];
                }
                const int k0 = (n - 1) >> 1;
                ull a = 0ull, b = 0ull;
#pragma unroll
                for (int u = 0; u < 6; u++)  FMA2(a, w2[u],      W[(k0 + u) % 12], a);
#pragma unroll
                for (int u = 6; u < 12; u++) FMA2(b, w2[11 - u], W[(k0 + u) % 12], b);
                ADD2(m2, a, b);
            } else {
                m2 = W[(n / 2 + 5) % 12];
            }
#pragma unroll
            for (int k = 0; k < 16; k++) {
                const int u = n - k;
                if (u >= 0 && u < 12) FMA2(acc[k], W2(u), m2, acc[k]);
            }
            if (n >= 5 && n < 21)            // even output rows: direct copy
                *reinterpret_cast<ull*>(&ob[(2 * (n - 5)) * 1024]) = m2;
            if (n >= 11) {                   // acc[n-11] is complete: retire now
                const int k = n - 11;
                *reinterpret_cast<ull*>(&ob[(2 * k + 1) * 1024]) = acc[k];
            }
        }
    }
}

extern "C" void kernel_launch(void* const* d_in, const int* in_sizes, int n_in,
                              void* d_out, int out_size)
{
    const float* x    = (const float*)d_in[0];   // (4,8,256,256) fp32
    const float* kern = (const float*)d_in[1];   // 23 taps fp32
    float* out = (float*)d_out;                  // (4,8,1024,1024) fp32

    fused_up4x<<<dim3(8, 8, 32), 256>>>(x, kern, out);
}